// round 9
// baseline (speedup 1.0000x reference)
#include <cuda_runtime.h>
#include <math.h>

#define GDIM 128
#define G3 (GDIM*GDIM*GDIM)
#define NPART 4096
#define NKEY 512           // 32 c0-bins (width 4) x 16 c1-subbins (width 8)
#define NSORT 32           // sort blocks (128 particles each)
#define SEGN 7             // max c0-bin segments per sample window
#define NBLOCK 2048        // total blocks (4 samples each)

// Scratch (__device__ globals, no allocation)
__device__ float4 g_ps[NPART * 2];      // [2p]=(gp0,gp1,gp2,omega) [2p+1]=(em0..3)
__device__ int    g_pcs[NPART + 32];    // packed floor cell
__device__ int    g_bs2[NKEY + 1];      // key -> global start offset
__device__ int    g_hist[NSORT * NKEY]; // per-block key histograms
__device__ int    g_bar1;               // sort-internal barrier
__device__ int    g_bar2;               // sort-completion counter
__device__ int    g_bar3;               // end-of-kernel reset counter
__device__ volatile int g_done;         // sort-done flag

struct SortSmem {
    int h[NKEY];                        // 2KB  block histogram
    int wsum[4];
    unsigned short bs2s[NKEY];          // 1KB  global key offsets (<=4096)
    unsigned short boffm[NKEY];         // 1KB  this block's cross-block offset
    unsigned short wcnt[4][NKEY];       // 4KB  per-warp stable-rank counters
};
union SmemU {
    SortSmem srt;
    float sv[4][5][64];                 // 5KB  epilogue cells (4 warps)
};

__global__ void __launch_bounds__(128, 10)
fused_kernel(const float* __restrict__ pos,
             const float* __restrict__ inten,
             const float* __restrict__ emo,
             const float* __restrict__ spos,
             const float* __restrict__ H0,
             const float* __restrict__ E0,
             float* __restrict__ out) {
    __shared__ SmemU u;
    const int tid  = threadIdx.x;
    const int w    = tid >> 5;
    const int lane = tid & 31;
    const unsigned FULL = 0xffffffffu;

    // ================= SORT PHASE (blocks 0..31) =================
    if (blockIdx.x < NSORT) {
        const int myb = blockIdx.x;
#pragma unroll
        for (int k = 0; k < NKEY / 128; k++) u.srt.h[tid + k * 128] = 0;
        __syncthreads();

        // key + payload + block histogram
        const int i = myb * 128 + tid;
        const float gp0 = (pos[3*i+0] + 1.0f) * 63.5f;
        const float gp1 = (pos[3*i+1] + 1.0f) * 63.5f;
        const float gp2 = (pos[3*i+2] + 1.0f) * 63.5f;
        const int c0 = min(max((int)floorf(gp0), 0), GDIM-1);
        const int c1 = min(max((int)floorf(gp1), 0), GDIM-1);
        const int c2 = min(max((int)floorf(gp2), 0), GDIM-1);
        const int pc  = c0 | (c1 << 8) | (c2 << 16);
        const int key = ((c0 >> 2) << 4) | (c1 >> 3);
        atomicAdd(&u.srt.h[key], 1);
        const float4 pA = make_float4(gp0, gp1, gp2, inten[i] * 0.01f);
        const float4 pE = make_float4(emo[4*i+0], emo[4*i+1], emo[4*i+2], emo[4*i+3]);
        __syncthreads();
#pragma unroll
        for (int k = 0; k < NKEY / 128; k++) {
            const int t = tid + k * 128;
            g_hist[myb * NKEY + t] = u.srt.h[t];
        }
        __threadfence();
        if (tid == 0) {
            atomicAdd(&g_bar1, 1);
            while (*(volatile int*)&g_bar1 < NSORT) { }
        }
        __syncthreads();
        __threadfence();

        // per-key cross-block sums; thread t owns keys 4t..4t+3
        int totk[4], bok[4];
#pragma unroll
        for (int k = 0; k < 4; k++) {
            const int kk = tid * 4 + k;
            int s2 = 0, mine = 0;
#pragma unroll
            for (int b = 0; b < NSORT; b++) {
                if (b == myb) mine = s2;
                s2 += g_hist[b * NKEY + kk];
            }
            totk[k] = s2; bok[k] = mine;
        }
        const int tsum = totk[0] + totk[1] + totk[2] + totk[3];
        int inc = tsum;
#pragma unroll
        for (int d = 1; d < 32; d <<= 1) {
            const int x = __shfl_up_sync(FULL, inc, d);
            if (lane >= d) inc += x;
        }
        if (lane == 31) u.srt.wsum[w] = inc;
        __syncthreads();
        if (tid == 0) {
            int s2 = 0;
#pragma unroll
            for (int q = 0; q < 4; q++) { const int x = u.srt.wsum[q]; u.srt.wsum[q] = s2; s2 += x; }
        }
        __syncthreads();
        int run = u.srt.wsum[w] + inc - tsum;   // exclusive prefix for key 4*tid
#pragma unroll
        for (int k = 0; k < 4; k++) {
            const int kk = tid * 4 + k;
            u.srt.bs2s[kk]  = (unsigned short)run;
            u.srt.boffm[kk] = (unsigned short)bok[k];
            run += totk[k];
        }
        __syncthreads();
        if (myb == 0) {
#pragma unroll
            for (int k = 0; k < 4; k++) {
                const int kk = tid * 4 + k;
                g_bs2[kk] = u.srt.bs2s[kk];
            }
            if (tid == 0) g_bs2[NKEY] = NPART;
        }

        // stable in-block ranks + scatter
#pragma unroll
        for (int k = 0; k < 8; k++) ((int*)u.srt.wcnt)[tid + k * 128] = 0;
        __syncthreads();
        const unsigned m = __match_any_sync(FULL, key);
        const int r = __popc(m & ((1u << lane) - 1u));
        if (r == 0) u.srt.wcnt[w][key] = (unsigned short)__popc(m);
        __syncthreads();
#pragma unroll
        for (int k = 0; k < 4; k++) {
            const int t = tid * 4 + k;
            int s2 = 0;
#pragma unroll
            for (int wi = 0; wi < 4; wi++) {
                const int v = u.srt.wcnt[wi][t];
                u.srt.wcnt[wi][t] = (unsigned short)s2;
                s2 += v;
            }
        }
        __syncthreads();
        const int p = (int)u.srt.bs2s[key] + (int)u.srt.boffm[key]
                    + (int)u.srt.wcnt[w][key] + r;
        g_pcs[p]      = pc;
        g_ps[2*p + 0] = pA;
        g_ps[2*p + 1] = pE;
        __threadfence();
        __syncthreads();
        if (tid == 0) {
            const int v = atomicAdd(&g_bar2, 1);
            if (v == NSORT - 1) { __threadfence(); g_done = 1; }
        }
    }

    // ================= GATE: wait for sort =================
    if (tid == 0) {
        while (g_done == 0) __nanosleep(64);
    }
    __syncthreads();
    __threadfence();

    // ================= MAIN PHASE: one warp per sample =================
    const int s = (blockIdx.x << 2) + w;

    const float px = spos[3*s+0];
    const float py = spos[3*s+1];
    const float pz = spos[3*s+2];
    // grid axis0 <- comp2, axis1 <- comp1, axis2 <- comp0 (reference transpose)
    const float t0 = fminf(fmaxf((pz + 1.0f) * 63.5f, 0.0f), 127.0f);
    const float t1 = fminf(fmaxf((py + 1.0f) * 63.5f, 0.0f), 127.0f);
    const float t2 = fminf(fmaxf((px + 1.0f) * 63.5f, 0.0f), 127.0f);
    const int i0 = (int)floorf(t0); const float f0 = t0 - (float)i0;
    const int i1 = (int)floorf(t1); const float f1 = t1 - (float)i1;
    const int i2 = (int)floorf(t2); const float f2 = t2 - (float)i2;

    // lane -> block coords (b0,b1,b2): 8 trilinear corners + 24 face neighbors
    int b0, b1, b2;
    if (lane < 8) {
        b0 = 1 + ((lane >> 2) & 1); b1 = 1 + ((lane >> 1) & 1); b2 = 1 + (lane & 1);
    } else {
        const int idx = lane - 8, axis = idx >> 3, rest = idx & 7;
        const int s3 = ((rest >> 2) & 1) * 3;
        const int uu = 1 + ((rest >> 1) & 1), vv = 1 + (rest & 1);
        b0 = (axis == 0) ? s3 : uu;
        b1 = (axis == 1) ? s3 : ((axis == 0) ? uu : vv);
        b2 = (axis == 2) ? s3 : vv;
    }
    const int gc0 = min(max(i0 - 1 + b0, 0), 127);
    const int gc1 = min(max(i1 - 1 + b1, 0), 127);
    const int gc2 = min(max(i2 - 1 + b2, 0), 127);
    const float gcf0 = (float)gc0, gcf1 = (float)gc1, gcf2 = (float)gc2;
    const unsigned gcpack = (unsigned)(gc0 | (gc1 << 8) | (gc2 << 16));

    // particle-window (covers all 32 cells)
    const int lo0 = min(max(i0 - 1, 0), 127) - 9, hi0 = min(max(i0 + 2, 0), 127) + 9;
    const int lo1 = min(max(i1 - 1, 0), 127) - 9, hi1 = min(max(i1 + 2, 0), 127) + 9;
    const int lo2 = min(max(i2 - 1, 0), 127) - 9, hi2 = min(max(i2 + 2, 0), 127) + 9;
    const unsigned sp0 = (unsigned)(hi0 - lo0);
    const unsigned sp1 = (unsigned)(hi1 - lo1);
    const unsigned sp2 = (unsigned)(hi2 - lo2);

    const int r0  = max(lo0, 0) >> 2;
    const int r1  = min(hi0, 127) >> 2;
    const int slo = max(lo1, 0) >> 3;
    const int shi = min(hi1, 127) >> 3;
    const int nseg = r1 - r0;              // 0..6

    // one MLP burst: segment bounds (packed j0|j1<<16) + first-chunk cells
    int jjp[SEGN], pv[SEGN];
#pragma unroll
    for (int k = 0; k < SEGN; k++) {
        const bool val = (k <= nseg);
        const int rb = (r0 + k) << 4;
        const int a = val ? __ldg(&g_bs2[rb + slo])     : 0;
        const int b = val ? __ldg(&g_bs2[rb + shi + 1]) : 0;
        jjp[k] = a | (b << 16);
    }
#pragma unroll
    for (int k = 0; k < SEGN; k++) {
        pv[k] = __ldg(&g_pcs[((jjp[k] & 0xFFFF) & ~31) + lane]);
    }

    // accumulators start from the base grid values
    const int flat = (gc0 * GDIM + gc1) * GDIM + gc2;
    float aH  = __ldg(&H0[flat]);
    float aE0 = __ldg(&E0[0*G3 + flat]);
    float aE1 = __ldg(&E0[1*G3 + flat]);
    float aE2 = __ldg(&E0[2*G3 + flat]);
    float aE3 = __ldg(&E0[3*G3 + flat]);

#pragma unroll
    for (int k = 0; k < SEGN; k++) {
        if (k > nseg) break;
        const int j0 = jjp[k] & 0xFFFF;
        const int j1 = jjp[k] >> 16;
        int base = j0 & ~31;
        int pcv  = pv[k];
        while (true) {
            const int  nbase = base + 32;
            const bool more  = nbase < j1;
            int npcv = 0;
            if (more) npcv = __ldg(&g_pcs[nbase + lane]);   // prefetch next chunk
            const int idx = base + lane;
            const int c0 = pcv & 255, c1 = (pcv >> 8) & 255, c2 = (pcv >> 16) & 255;
            const bool hit = ((unsigned)(c0 - lo0) <= sp0) &
                             ((unsigned)(c1 - lo1) <= sp1) &
                             ((unsigned)(c2 - lo2) <= sp2) &
                             (idx >= j0) & (idx < j1);
            unsigned msk = __ballot_sync(FULL, hit);
            while (msk) {
                const int j = __ffs(msk) - 1;
                msk &= msk - 1;
                const int pcj = __shfl_sync(FULL, pcv, j);
                const float4 A  = __ldg(&g_ps[2*(base + j) + 0]);
                const float4 Em = __ldg(&g_ps[2*(base + j) + 1]);
                const unsigned diff = __vabsdiffu4((unsigned)pcj, gcpack);
                const bool in = (__vcmpleu4(diff, 0x09090909u) == 0xFFFFFFFFu);
                const float d0 = gcf0 - A.x;
                const float d1 = gcf1 - A.y;
                const float d2 = gcf2 - A.z;
                const float ssum = fmaf(d0, d0, fmaf(d1, d1, d2 * d2));
                const float e = __expf(ssum * -0.048828125f);
                float wv = in ? A.w : 0.0f;
                wv *= e;
                aH  += wv;
                aE0 += wv * Em.x;  aE1 += wv * Em.y;
                aE2 += wv * Em.z;  aE3 += wv * Em.w;
            }
            if (!more) break;
            base = nbase; pcv = npcv;
        }
    }

    // stash the 32 needed cells in shared (union reuse is safe: sort phase
    // finished before the gate for all blocks)
    __syncthreads();
    const int ci = b0 * 16 + b1 * 4 + b2;
    u.sv[w][0][ci] = aH;
    u.sv[w][1][ci] = aE0;
    u.sv[w][2][ci] = aE1;
    u.sv[w][3][ci] = aE2;
    u.sv[w][4][ci] = aE3;
    __syncwarp();

    // diffusion step + ReLU + trilinear reduce (8 corner lanes)
#pragma unroll
    for (int ch = 0; ch < 5; ch++) {
        float part = 0.0f;
        if (lane < 8) {
            const int d0 = (lane >> 2) & 1, d1c = (lane >> 1) & 1, d2c = lane & 1;
            const int cc = (1 + d0) * 16 + (1 + d1c) * 4 + (1 + d2c);
            const float* v = u.sv[w][ch];
            const float c = v[cc];
            const float lap = v[cc-16] + v[cc+16] + v[cc-4] + v[cc+4]
                            + v[cc-1]  + v[cc+1]  - 6.0f * c;
            float val;
            if (ch == 0) val = c * (1.0f - 5e-5f) + 0.002f * lap;
            else         val = c * (1.0f - 5e-5f) + 5e-5f + 0.001f * lap;
            val = fmaxf(val, 0.0f);
            const float wq = (d0  ? f0 : 1.0f - f0)
                           * (d1c ? f1 : 1.0f - f1)
                           * (d2c ? f2 : 1.0f - f2);
            part = val * wq;
        }
        part += __shfl_down_sync(FULL, part, 4);
        part += __shfl_down_sync(FULL, part, 2);
        part += __shfl_down_sync(FULL, part, 1);
        if (lane == 0) out[s * 5 + ch] = part;
    }

    // ---- self-reset for the next graph replay ----
    __syncthreads();
    if (tid == 0) {
        const int v = atomicAdd(&g_bar3, 1);
        if (v == NBLOCK - 1) {
            g_bar1 = 0; g_bar2 = 0; g_bar3 = 0; g_done = 0;
            __threadfence();
        }
    }
}

extern "C" void kernel_launch(void* const* d_in, const int* in_sizes, int n_in,
                              void* d_out, int out_size) {
    const float* positions   = (const float*)d_in[0];  // (4096,3)
    const float* intensities = (const float*)d_in[1];  // (4096,)
    const float* emotions    = (const float*)d_in[2];  // (4096,4)
    const float* sample_pos  = (const float*)d_in[3];  // (8,1024,3)
    const float* H0          = (const float*)d_in[4];  // (128,128,128)
    const float* E0          = (const float*)d_in[5];  // (4,128,128,128)
    float* out = (float*)d_out;                        // (8,1024,5)

    fused_kernel<<<NBLOCK, 128>>>(positions, intensities, emotions,
                                  sample_pos, H0, E0, out);
    (void)in_sizes; (void)n_in; (void)out_size;
}

// round 10
// speedup vs baseline: 1.0026x; 1.0026x over previous
#include <cuda_runtime.h>
#include <math.h>

#define GDIM 128
#define G3 (GDIM*GDIM*GDIM)
#define NPART 4096
#define NKEY 512           // 32 c0-bins (width 4) x 16 c1-subbins (width 8)
#define NBLK 32            // sort blocks (128 particles each)
#define SEGN 7             // max c0-bin segments per sample window

// Scratch (__device__ globals, no allocation)
__device__ float4 g_ps[NPART * 2];      // [2p]=(gp0,gp1,gp2,omega) [2p+1]=(em0..3)
__device__ int    g_pcs[NPART + 32];    // packed floor cell
__device__ int    g_bs2[NKEY + 1];      // key -> global start offset
__device__ int    g_hist[NBLK * NKEY];  // per-block key histograms
__device__ int    g_bar1;               // spin barrier (self-resetting)
__device__ int    g_bar2;

// ---------------------------------------------------------------------------
// Fused sort: hist + cross-block offsets + stable scatter in ONE kernel.
// 32 blocks x 128 threads; device spin barrier (32 blocks always co-resident).
// ---------------------------------------------------------------------------
__global__ void __launch_bounds__(128)
fsort_kernel(const float* __restrict__ pos,
             const float* __restrict__ inten,
             const float* __restrict__ emo) {
    __shared__ int h[NKEY];
    __shared__ int bs2s[NKEY];
    __shared__ int boffm[NKEY];
    __shared__ int wcnt[4][NKEY];
    __shared__ int wsum[4];
    const int tid  = threadIdx.x;
    const int w    = tid >> 5;
    const int lane = tid & 31;
    const int myb  = blockIdx.x;
    const unsigned FULL = 0xffffffffu;

#pragma unroll
    for (int k = 0; k < NKEY / 128; k++) h[tid + k * 128] = 0;
    __syncthreads();

    // ---- phase A: key + payload + block histogram ----
    const int i = myb * 128 + tid;
    const float gp0 = (pos[3*i+0] + 1.0f) * 63.5f;
    const float gp1 = (pos[3*i+1] + 1.0f) * 63.5f;
    const float gp2 = (pos[3*i+2] + 1.0f) * 63.5f;
    const int c0 = min(max((int)floorf(gp0), 0), GDIM-1);
    const int c1 = min(max((int)floorf(gp1), 0), GDIM-1);
    const int c2 = min(max((int)floorf(gp2), 0), GDIM-1);
    const int pc  = c0 | (c1 << 8) | (c2 << 16);
    const int key = ((c0 >> 2) << 4) | (c1 >> 3);
    atomicAdd(&h[key], 1);
    const float4 pA = make_float4(gp0, gp1, gp2, inten[i] * 0.01f);
    const float4 pE = make_float4(emo[4*i+0], emo[4*i+1], emo[4*i+2], emo[4*i+3]);
    __syncthreads();
#pragma unroll
    for (int k = 0; k < NKEY / 128; k++) {
        const int t = tid + k * 128;
        g_hist[myb * NKEY + t] = h[t];
    }
    __threadfence();

    // ---- barrier: all block histograms visible ----
    if (tid == 0) {
        atomicAdd(&g_bar1, 1);
        while (*(volatile int*)&g_bar1 < NBLK) { }
    }
    __syncthreads();
    __threadfence();

    // ---- phase B: per-key cross-block sums; thread t owns keys 4t..4t+3 ----
    int totk[4], bok[4];
#pragma unroll
    for (int k = 0; k < 4; k++) {
        const int kk = tid * 4 + k;
        int s = 0, mine = 0;
#pragma unroll
        for (int b = 0; b < NBLK; b++) {
            if (b == myb) mine = s;
            s += g_hist[b * NKEY + kk];
        }
        totk[k] = s; bok[k] = mine;
    }
    const int tsum = totk[0] + totk[1] + totk[2] + totk[3];
    int inc = tsum;
#pragma unroll
    for (int d = 1; d < 32; d <<= 1) {
        const int u = __shfl_up_sync(FULL, inc, d);
        if (lane >= d) inc += u;
    }
    if (lane == 31) wsum[w] = inc;
    __syncthreads();
    if (tid == 0) {
        int s = 0;
#pragma unroll
        for (int q = 0; q < 4; q++) { const int x = wsum[q]; wsum[q] = s; s += x; }
    }
    __syncthreads();
    int run = wsum[w] + inc - tsum;        // exclusive prefix for key 4*tid
#pragma unroll
    for (int k = 0; k < 4; k++) {
        const int kk = tid * 4 + k;
        bs2s[kk]  = run;
        boffm[kk] = bok[k];
        run += totk[k];
    }
    __syncthreads();
    if (myb == 0) {
#pragma unroll
        for (int k = 0; k < 4; k++) {
            const int kk = tid * 4 + k;
            g_bs2[kk] = bs2s[kk];
        }
        if (tid == 0) g_bs2[NKEY] = NPART;
    }

    // ---- phase C: stable in-block ranks + scatter ----
#pragma unroll
    for (int k = 0; k < 4 * NKEY / 128; k++) ((int*)wcnt)[tid + k * 128] = 0;
    __syncthreads();
    const unsigned m = __match_any_sync(FULL, key);
    const int r = __popc(m & ((1u << lane) - 1u));
    if (r == 0) wcnt[w][key] = __popc(m);
    __syncthreads();
#pragma unroll
    for (int k = 0; k < NKEY / 128; k++) {
        const int t = tid + k * 128;
        int s = 0;
#pragma unroll
        for (int wi = 0; wi < 4; wi++) { const int v = wcnt[wi][t]; wcnt[wi][t] = s; s += v; }
    }
    __syncthreads();

    const int p = bs2s[key] + boffm[key] + wcnt[w][key] + r;
    g_pcs[p]      = pc;
    g_ps[2*p + 0] = pA;
    g_ps[2*p + 1] = pE;

    // ---- self-reset barrier counters for next replay ----
    __syncthreads();
    if (tid == 0) {
        const int v = atomicAdd(&g_bar2, 1);
        if (v == NBLK - 1) { g_bar1 = 0; g_bar2 = 0; __threadfence(); }
    }
}

// ---------------------------------------------------------------------------
// One warp per sample. Each lane owns ONE of the 32 cells actually needed.
// Segment bounds are packed (j0 | j1<<16) to halve prefetch register cost;
// launch bounds cap regs at ~48 for ~65% theoretical occupancy.
// ---------------------------------------------------------------------------
__global__ void __launch_bounds__(64, 21)
main_kernel(const float* __restrict__ spos,
            const float* __restrict__ H0,
            const float* __restrict__ E0,
            float* __restrict__ out) {
    __shared__ float sv[2][5][64];
    const unsigned FULL = 0xffffffffu;
    const int wib  = threadIdx.x >> 5;
    const int lane = threadIdx.x & 31;
    const int s    = (blockIdx.x << 1) + wib;

    const float px = spos[3*s+0];
    const float py = spos[3*s+1];
    const float pz = spos[3*s+2];
    // grid axis0 <- comp2, axis1 <- comp1, axis2 <- comp0 (reference transpose)
    const float t0 = fminf(fmaxf((pz + 1.0f) * 63.5f, 0.0f), 127.0f);
    const float t1 = fminf(fmaxf((py + 1.0f) * 63.5f, 0.0f), 127.0f);
    const float t2 = fminf(fmaxf((px + 1.0f) * 63.5f, 0.0f), 127.0f);
    const int i0 = (int)floorf(t0); const float f0 = t0 - (float)i0;
    const int i1 = (int)floorf(t1); const float f1 = t1 - (float)i1;
    const int i2 = (int)floorf(t2); const float f2 = t2 - (float)i2;

    // lane -> block coords (b0,b1,b2), covering the 32 needed cells
    int b0, b1, b2;
    if (lane < 8) {
        b0 = 1 + ((lane >> 2) & 1); b1 = 1 + ((lane >> 1) & 1); b2 = 1 + (lane & 1);
    } else {
        const int idx = lane - 8, axis = idx >> 3, rest = idx & 7;
        const int s3 = ((rest >> 2) & 1) * 3;
        const int u = 1 + ((rest >> 1) & 1), v = 1 + (rest & 1);
        b0 = (axis == 0) ? s3 : u;
        b1 = (axis == 1) ? s3 : ((axis == 0) ? u : v);
        b2 = (axis == 2) ? s3 : v;
    }
    const int gc0 = min(max(i0 - 1 + b0, 0), 127);
    const int gc1 = min(max(i1 - 1 + b1, 0), 127);
    const int gc2 = min(max(i2 - 1 + b2, 0), 127);
    const float gcf0 = (float)gc0, gcf1 = (float)gc1, gcf2 = (float)gc2;
    const unsigned gcpack = (unsigned)(gc0 | (gc1 << 8) | (gc2 << 16));

    // particle-window (covers all 32 cells)
    const int lo0 = min(max(i0 - 1, 0), 127) - 9, hi0 = min(max(i0 + 2, 0), 127) + 9;
    const int lo1 = min(max(i1 - 1, 0), 127) - 9, hi1 = min(max(i1 + 2, 0), 127) + 9;
    const int lo2 = min(max(i2 - 1, 0), 127) - 9, hi2 = min(max(i2 + 2, 0), 127) + 9;
    const unsigned sp0 = (unsigned)(hi0 - lo0);
    const unsigned sp1 = (unsigned)(hi1 - lo1);
    const unsigned sp2 = (unsigned)(hi2 - lo2);

    const int r0  = max(lo0, 0) >> 2;
    const int r1  = min(hi0, 127) >> 2;
    const int slo = max(lo1, 0) >> 3;
    const int shi = min(hi1, 127) >> 3;
    const int nseg = r1 - r0;              // 0..6

    // one MLP burst: segment bounds (packed j0|j1<<16) + first-chunk cells
    int jjp[SEGN], pv[SEGN];
#pragma unroll
    for (int k = 0; k < SEGN; k++) {
        const bool val = (k <= nseg);
        const int rb = (r0 + k) << 4;
        const int a = val ? __ldg(&g_bs2[rb + slo])     : 0;
        const int b = val ? __ldg(&g_bs2[rb + shi + 1]) : 0;
        jjp[k] = a | (b << 16);
    }
#pragma unroll
    for (int k = 0; k < SEGN; k++) {
        pv[k] = __ldg(&g_pcs[((jjp[k] & 0xFFFF) & ~31) + lane]);
    }

    // accumulators start from the base grid values (loads overlap the scan)
    const int flat = (gc0 * GDIM + gc1) * GDIM + gc2;
    float aH  = __ldg(&H0[flat]);
    float aE0 = __ldg(&E0[0*G3 + flat]);
    float aE1 = __ldg(&E0[1*G3 + flat]);
    float aE2 = __ldg(&E0[2*G3 + flat]);
    float aE3 = __ldg(&E0[3*G3 + flat]);

#pragma unroll
    for (int k = 0; k < SEGN; k++) {
        if (k > nseg) break;
        const int j0 = jjp[k] & 0xFFFF;
        const int j1 = jjp[k] >> 16;
        int base = j0 & ~31;
        int pcv  = pv[k];
        while (true) {
            const int  nbase = base + 32;
            const bool more  = nbase < j1;
            int npcv = 0;
            if (more) npcv = __ldg(&g_pcs[nbase + lane]);   // prefetch next chunk
            const int idx = base + lane;
            const int c0 = pcv & 255, c1 = (pcv >> 8) & 255, c2 = (pcv >> 16) & 255;
            const bool hit = ((unsigned)(c0 - lo0) <= sp0) &
                             ((unsigned)(c1 - lo1) <= sp1) &
                             ((unsigned)(c2 - lo2) <= sp2) &
                             (idx >= j0) & (idx < j1);
            unsigned msk = __ballot_sync(FULL, hit);
            while (msk) {
                const int j = __ffs(msk) - 1;
                msk &= msk - 1;
                const int pcj = __shfl_sync(FULL, pcv, j);
                const float4 A  = __ldg(&g_ps[2*(base + j) + 0]);
                const float4 Em = __ldg(&g_ps[2*(base + j) + 1]);
                const unsigned diff = __vabsdiffu4((unsigned)pcj, gcpack);
                const bool in = (__vcmpleu4(diff, 0x09090909u) == 0xFFFFFFFFu);
                const float d0 = gcf0 - A.x;
                const float d1 = gcf1 - A.y;
                const float d2 = gcf2 - A.z;
                const float ssum = fmaf(d0, d0, fmaf(d1, d1, d2 * d2));
                const float e = __expf(ssum * -0.048828125f);
                float wv = in ? A.w : 0.0f;
                wv *= e;
                aH  += wv;
                aE0 += wv * Em.x;  aE1 += wv * Em.y;
                aE2 += wv * Em.z;  aE3 += wv * Em.w;
            }
            if (!more) break;
            base = nbase; pcv = npcv;
        }
    }

    // stash the 32 needed cells in shared
    const int ci = b0 * 16 + b1 * 4 + b2;
    sv[wib][0][ci] = aH;
    sv[wib][1][ci] = aE0;
    sv[wib][2][ci] = aE1;
    sv[wib][3][ci] = aE2;
    sv[wib][4][ci] = aE3;
    __syncwarp();

    // diffusion step + ReLU + trilinear reduce (8 corner lanes)
#pragma unroll
    for (int ch = 0; ch < 5; ch++) {
        float part = 0.0f;
        if (lane < 8) {
            const int d0 = (lane >> 2) & 1, d1c = (lane >> 1) & 1, d2c = lane & 1;
            const int cc = (1 + d0) * 16 + (1 + d1c) * 4 + (1 + d2c);
            const float* v = sv[wib][ch];
            const float c = v[cc];
            const float lap = v[cc-16] + v[cc+16] + v[cc-4] + v[cc+4]
                            + v[cc-1]  + v[cc+1]  - 6.0f * c;
            float val;
            if (ch == 0) val = c * (1.0f - 5e-5f) + 0.002f * lap;
            else         val = c * (1.0f - 5e-5f) + 5e-5f + 0.001f * lap;
            val = fmaxf(val, 0.0f);
            const float wq = (d0  ? f0 : 1.0f - f0)
                           * (d1c ? f1 : 1.0f - f1)
                           * (d2c ? f2 : 1.0f - f2);
            part = val * wq;
        }
        part += __shfl_down_sync(FULL, part, 4);
        part += __shfl_down_sync(FULL, part, 2);
        part += __shfl_down_sync(FULL, part, 1);
        if (lane == 0) out[s * 5 + ch] = part;
    }
}

extern "C" void kernel_launch(void* const* d_in, const int* in_sizes, int n_in,
                              void* d_out, int out_size) {
    const float* positions   = (const float*)d_in[0];  // (4096,3)
    const float* intensities = (const float*)d_in[1];  // (4096,)
    const float* emotions    = (const float*)d_in[2];  // (4096,4)
    const float* sample_pos  = (const float*)d_in[3];  // (8,1024,3)
    const float* H0          = (const float*)d_in[4];  // (128,128,128)
    const float* E0          = (const float*)d_in[5];  // (4,128,128,128)
    float* out = (float*)d_out;                        // (8,1024,5)

    fsort_kernel<<<NBLK, 128>>>(positions, intensities, emotions);
    main_kernel<<<4096, 64>>>(sample_pos, H0, E0, out);
    (void)in_sizes; (void)n_in; (void)out_size;
}

// round 11
// speedup vs baseline: 1.0607x; 1.0580x over previous
#include <cuda_runtime.h>
#include <math.h>

#define GDIM 128
#define G3 (GDIM*GDIM*GDIM)
#define NPART 4096
#define NKEY 512           // 32 c0-bins (width 4) x 16 c1-subbins (width 8)
#define NBLK 32            // sort blocks (128 particles each)
#define SEGN 7             // max c0-bin segments per sample window

// Scratch (__device__ globals, no allocation)
__device__ float4 g_ps[NPART * 2];      // [2p]=(gp0,gp1,gp2,omega) [2p+1]=(em0..3)
__device__ int    g_pcs[NPART + 32];    // packed floor cell
__device__ int    g_bs2[NKEY + 1];      // key -> global start offset
__device__ int    g_hist[NBLK * NKEY];  // per-block key histograms
__device__ int    g_bar1;               // spin barrier (self-resetting)
__device__ int    g_bar2;

// ---------------------------------------------------------------------------
// Fused sort: hist + cross-block offsets + stable scatter in ONE kernel.
// 32 blocks x 128 threads; device spin barrier (32 blocks always co-resident).
// ---------------------------------------------------------------------------
__global__ void __launch_bounds__(128)
fsort_kernel(const float* __restrict__ pos,
             const float* __restrict__ inten,
             const float* __restrict__ emo) {
    __shared__ int h[NKEY];
    __shared__ int bs2s[NKEY];
    __shared__ int boffm[NKEY];
    __shared__ int wcnt[4][NKEY];
    __shared__ int wsum[4];
    const int tid  = threadIdx.x;
    const int w    = tid >> 5;
    const int lane = tid & 31;
    const int myb  = blockIdx.x;
    const unsigned FULL = 0xffffffffu;

#pragma unroll
    for (int k = 0; k < NKEY / 128; k++) h[tid + k * 128] = 0;
    __syncthreads();

    // ---- phase A: key + payload + block histogram ----
    const int i = myb * 128 + tid;
    const float gp0 = (pos[3*i+0] + 1.0f) * 63.5f;
    const float gp1 = (pos[3*i+1] + 1.0f) * 63.5f;
    const float gp2 = (pos[3*i+2] + 1.0f) * 63.5f;
    const int c0 = min(max((int)floorf(gp0), 0), GDIM-1);
    const int c1 = min(max((int)floorf(gp1), 0), GDIM-1);
    const int c2 = min(max((int)floorf(gp2), 0), GDIM-1);
    const int pc  = c0 | (c1 << 8) | (c2 << 16);
    const int key = ((c0 >> 2) << 4) | (c1 >> 3);
    atomicAdd(&h[key], 1);
    const float4 pA = make_float4(gp0, gp1, gp2, inten[i] * 0.01f);
    const float4 pE = make_float4(emo[4*i+0], emo[4*i+1], emo[4*i+2], emo[4*i+3]);
    __syncthreads();
#pragma unroll
    for (int k = 0; k < NKEY / 128; k++) {
        const int t = tid + k * 128;
        g_hist[myb * NKEY + t] = h[t];
    }
    __threadfence();

    // ---- barrier: all block histograms visible ----
    if (tid == 0) {
        atomicAdd(&g_bar1, 1);
        while (*(volatile int*)&g_bar1 < NBLK) { }
    }
    __syncthreads();
    __threadfence();

    // ---- phase B: per-key cross-block sums; thread t owns keys 4t..4t+3 ----
    int totk[4], bok[4];
#pragma unroll
    for (int k = 0; k < 4; k++) {
        const int kk = tid * 4 + k;
        int s = 0, mine = 0;
#pragma unroll
        for (int b = 0; b < NBLK; b++) {
            if (b == myb) mine = s;
            s += g_hist[b * NKEY + kk];
        }
        totk[k] = s; bok[k] = mine;
    }
    const int tsum = totk[0] + totk[1] + totk[2] + totk[3];
    int inc = tsum;
#pragma unroll
    for (int d = 1; d < 32; d <<= 1) {
        const int u = __shfl_up_sync(FULL, inc, d);
        if (lane >= d) inc += u;
    }
    if (lane == 31) wsum[w] = inc;
    __syncthreads();
    if (tid == 0) {
        int s = 0;
#pragma unroll
        for (int q = 0; q < 4; q++) { const int x = wsum[q]; wsum[q] = s; s += x; }
    }
    __syncthreads();
    int run = wsum[w] + inc - tsum;        // exclusive prefix for key 4*tid
#pragma unroll
    for (int k = 0; k < 4; k++) {
        const int kk = tid * 4 + k;
        bs2s[kk]  = run;
        boffm[kk] = bok[k];
        run += totk[k];
    }
    __syncthreads();
    if (myb == 0) {
#pragma unroll
        for (int k = 0; k < 4; k++) {
            const int kk = tid * 4 + k;
            g_bs2[kk] = bs2s[kk];
        }
        if (tid == 0) g_bs2[NKEY] = NPART;
    }

    // ---- phase C: stable in-block ranks + scatter ----
#pragma unroll
    for (int k = 0; k < 4 * NKEY / 128; k++) ((int*)wcnt)[tid + k * 128] = 0;
    __syncthreads();
    const unsigned m = __match_any_sync(FULL, key);
    const int r = __popc(m & ((1u << lane) - 1u));
    if (r == 0) wcnt[w][key] = __popc(m);
    __syncthreads();
#pragma unroll
    for (int k = 0; k < NKEY / 128; k++) {
        const int t = tid + k * 128;
        int s = 0;
#pragma unroll
        for (int wi = 0; wi < 4; wi++) { const int v = wcnt[wi][t]; wcnt[wi][t] = s; s += v; }
    }
    __syncthreads();

    const int p = bs2s[key] + boffm[key] + wcnt[w][key] + r;
    g_pcs[p]      = pc;
    g_ps[2*p + 0] = pA;
    g_ps[2*p + 1] = pE;

    // ---- self-reset barrier counters for next replay ----
    __syncthreads();
    if (tid == 0) {
        const int v = atomicAdd(&g_bar2, 1);
        if (v == NBLK - 1) { g_bar1 = 0; g_bar2 = 0; __threadfence(); }
    }
}

// ---------------------------------------------------------------------------
// ONE WARP PER BLOCK, one sample per warp (no intra-block tail co-wait).
// Each lane owns ONE of the 32 cells actually needed: 8 trilinear corners
// + their 24 face neighbors. All segment bounds + first-chunk cell words are
// prefetched in one MLP burst before the scan.
// ---------------------------------------------------------------------------
__global__ void __launch_bounds__(32)
main_kernel(const float* __restrict__ spos,
            const float* __restrict__ H0,
            const float* __restrict__ E0,
            float* __restrict__ out) {
    __shared__ float sv[5][64];
    const unsigned FULL = 0xffffffffu;
    const int lane = threadIdx.x;
    const int s    = blockIdx.x;

    const float px = spos[3*s+0];
    const float py = spos[3*s+1];
    const float pz = spos[3*s+2];
    // grid axis0 <- comp2, axis1 <- comp1, axis2 <- comp0 (reference transpose)
    const float t0 = fminf(fmaxf((pz + 1.0f) * 63.5f, 0.0f), 127.0f);
    const float t1 = fminf(fmaxf((py + 1.0f) * 63.5f, 0.0f), 127.0f);
    const float t2 = fminf(fmaxf((px + 1.0f) * 63.5f, 0.0f), 127.0f);
    const int i0 = (int)floorf(t0); const float f0 = t0 - (float)i0;
    const int i1 = (int)floorf(t1); const float f1 = t1 - (float)i1;
    const int i2 = (int)floorf(t2); const float f2 = t2 - (float)i2;

    // lane -> block coords (b0,b1,b2), covering the 32 needed cells
    int b0, b1, b2;
    if (lane < 8) {
        b0 = 1 + ((lane >> 2) & 1); b1 = 1 + ((lane >> 1) & 1); b2 = 1 + (lane & 1);
    } else {
        const int idx = lane - 8, axis = idx >> 3, rest = idx & 7;
        const int s3 = ((rest >> 2) & 1) * 3;
        const int u = 1 + ((rest >> 1) & 1), v = 1 + (rest & 1);
        b0 = (axis == 0) ? s3 : u;
        b1 = (axis == 1) ? s3 : ((axis == 0) ? u : v);
        b2 = (axis == 2) ? s3 : v;
    }
    const int gc0 = min(max(i0 - 1 + b0, 0), 127);
    const int gc1 = min(max(i1 - 1 + b1, 0), 127);
    const int gc2 = min(max(i2 - 1 + b2, 0), 127);
    const float gcf0 = (float)gc0, gcf1 = (float)gc1, gcf2 = (float)gc2;
    const unsigned gcpack = (unsigned)(gc0 | (gc1 << 8) | (gc2 << 16));

    // particle-window (covers all 32 cells)
    const int lo0 = min(max(i0 - 1, 0), 127) - 9, hi0 = min(max(i0 + 2, 0), 127) + 9;
    const int lo1 = min(max(i1 - 1, 0), 127) - 9, hi1 = min(max(i1 + 2, 0), 127) + 9;
    const int lo2 = min(max(i2 - 1, 0), 127) - 9, hi2 = min(max(i2 + 2, 0), 127) + 9;
    const unsigned sp0 = (unsigned)(hi0 - lo0);
    const unsigned sp1 = (unsigned)(hi1 - lo1);
    const unsigned sp2 = (unsigned)(hi2 - lo2);

    const int r0  = max(lo0, 0) >> 2;
    const int r1  = min(hi0, 127) >> 2;
    const int slo = max(lo1, 0) >> 3;
    const int shi = min(hi1, 127) >> 3;
    const int nseg = r1 - r0;              // 0..6

    // ---- one MLP burst: all segment bounds + first-chunk cell words ----
    int jj0[SEGN], jj1[SEGN], pv[SEGN];
#pragma unroll
    for (int k = 0; k < SEGN; k++) {
        const bool val = (k <= nseg);
        const int rb = (r0 + k) << 4;
        jj0[k] = val ? __ldg(&g_bs2[rb + slo])     : 0;
        jj1[k] = val ? __ldg(&g_bs2[rb + shi + 1]) : 0;
    }
#pragma unroll
    for (int k = 0; k < SEGN; k++) {
        const bool val = (k <= nseg);
        pv[k] = __ldg(&g_pcs[(val ? (jj0[k] & ~31) : 0) + lane]);
    }

    // accumulators start from the base grid values (loads overlap the scan)
    const int flat = (gc0 * GDIM + gc1) * GDIM + gc2;
    float aH  = __ldg(&H0[flat]);
    float aE0 = __ldg(&E0[0*G3 + flat]);
    float aE1 = __ldg(&E0[1*G3 + flat]);
    float aE2 = __ldg(&E0[2*G3 + flat]);
    float aE3 = __ldg(&E0[3*G3 + flat]);

#pragma unroll
    for (int k = 0; k < SEGN; k++) {
        if (k > nseg) break;
        const int j0 = jj0[k], j1 = jj1[k];
        int base = j0 & ~31;
        int pcv  = pv[k];
        while (true) {
            const int  nbase = base + 32;
            const bool more  = nbase < j1;
            int npcv = 0;
            if (more) npcv = __ldg(&g_pcs[nbase + lane]);   // prefetch next chunk
            const int idx = base + lane;
            const int c0 = pcv & 255, c1 = (pcv >> 8) & 255, c2 = (pcv >> 16) & 255;
            const bool hit = ((unsigned)(c0 - lo0) <= sp0) &
                             ((unsigned)(c1 - lo1) <= sp1) &
                             ((unsigned)(c2 - lo2) <= sp2) &
                             (idx >= j0) & (idx < j1);
            unsigned msk = __ballot_sync(FULL, hit);
            while (msk) {
                const int j = __ffs(msk) - 1;
                msk &= msk - 1;
                const int pcj = __shfl_sync(FULL, pcv, j);
                const float4 A  = __ldg(&g_ps[2*(base + j) + 0]);
                const float4 Em = __ldg(&g_ps[2*(base + j) + 1]);
                const unsigned diff = __vabsdiffu4((unsigned)pcj, gcpack);
                const bool in = (__vcmpleu4(diff, 0x09090909u) == 0xFFFFFFFFu);
                const float d0 = gcf0 - A.x;
                const float d1 = gcf1 - A.y;
                const float d2 = gcf2 - A.z;
                const float ssum = fmaf(d0, d0, fmaf(d1, d1, d2 * d2));
                const float e = __expf(ssum * -0.048828125f);
                float wv = in ? A.w : 0.0f;
                wv *= e;
                aH  += wv;
                aE0 += wv * Em.x;  aE1 += wv * Em.y;
                aE2 += wv * Em.z;  aE3 += wv * Em.w;
            }
            if (!more) break;
            base = nbase; pcv = npcv;
        }
    }

    // stash the 32 needed cells in shared
    const int ci = b0 * 16 + b1 * 4 + b2;
    sv[0][ci] = aH;
    sv[1][ci] = aE0;
    sv[2][ci] = aE1;
    sv[3][ci] = aE2;
    sv[4][ci] = aE3;
    __syncwarp();

    // diffusion step + ReLU + trilinear reduce (8 corner lanes)
#pragma unroll
    for (int ch = 0; ch < 5; ch++) {
        float part = 0.0f;
        if (lane < 8) {
            const int d0 = (lane >> 2) & 1, d1c = (lane >> 1) & 1, d2c = lane & 1;
            const int cc = (1 + d0) * 16 + (1 + d1c) * 4 + (1 + d2c);
            const float* v = sv[ch];
            const float c = v[cc];
            const float lap = v[cc-16] + v[cc+16] + v[cc-4] + v[cc+4]
                            + v[cc-1]  + v[cc+1]  - 6.0f * c;
            float val;
            if (ch == 0) val = c * (1.0f - 5e-5f) + 0.002f * lap;
            else         val = c * (1.0f - 5e-5f) + 5e-5f + 0.001f * lap;
            val = fmaxf(val, 0.0f);
            const float wq = (d0  ? f0 : 1.0f - f0)
                           * (d1c ? f1 : 1.0f - f1)
                           * (d2c ? f2 : 1.0f - f2);
            part = val * wq;
        }
        part += __shfl_down_sync(FULL, part, 4);
        part += __shfl_down_sync(FULL, part, 2);
        part += __shfl_down_sync(FULL, part, 1);
        if (lane == 0) out[s * 5 + ch] = part;
    }
}

extern "C" void kernel_launch(void* const* d_in, const int* in_sizes, int n_in,
                              void* d_out, int out_size) {
    const float* positions   = (const float*)d_in[0];  // (4096,3)
    const float* intensities = (const float*)d_in[1];  // (4096,)
    const float* emotions    = (const float*)d_in[2];  // (4096,4)
    const float* sample_pos  = (const float*)d_in[3];  // (8,1024,3)
    const float* H0          = (const float*)d_in[4];  // (128,128,128)
    const float* E0          = (const float*)d_in[5];  // (4,128,128,128)
    float* out = (float*)d_out;                        // (8,1024,5)

    fsort_kernel<<<NBLK, 128>>>(positions, intensities, emotions);
    main_kernel<<<8192, 32>>>(sample_pos, H0, E0, out);
    (void)in_sizes; (void)n_in; (void)out_size;
}

// round 12
// speedup vs baseline: 1.0636x; 1.0027x over previous
#include <cuda_runtime.h>
#include <math.h>

#define GDIM 128
#define G3 (GDIM*GDIM*GDIM)
#define NPART 4096
#define NKEY 512           // 32 c0-bins (width 4) x 16 c1-subbins (width 8)
#define NBLK 32            // sort blocks (128 particles each)
#define SEGN 7             // max c0-bin segments per sample window

// Scratch (__device__ globals, no allocation)
__device__ float4 g_ps[NPART * 2];      // [2p]=(gp0,gp1,gp2,omega) [2p+1]=(em0..3)
__device__ int    g_pcs[NPART + 32];    // packed floor cell
__device__ int    g_bs2[NKEY + 1];      // key -> global start offset
__device__ int    g_hist[NBLK * NKEY];  // per-block key histograms
__device__ int    g_bar1;               // spin barrier (self-resetting)
__device__ int    g_bar2;

// ---------------------------------------------------------------------------
// Fused sort: hist + cross-block offsets + stable scatter in ONE kernel.
// 32 blocks x 128 threads; device spin barrier (32 blocks always co-resident).
// ---------------------------------------------------------------------------
__global__ void __launch_bounds__(128)
fsort_kernel(const float* __restrict__ pos,
             const float* __restrict__ inten,
             const float* __restrict__ emo) {
    __shared__ int h[NKEY];
    __shared__ int bs2s[NKEY];
    __shared__ int boffm[NKEY];
    __shared__ int wcnt[4][NKEY];
    __shared__ int wsum[4];
    const int tid  = threadIdx.x;
    const int w    = tid >> 5;
    const int lane = tid & 31;
    const int myb  = blockIdx.x;
    const unsigned FULL = 0xffffffffu;

#pragma unroll
    for (int k = 0; k < NKEY / 128; k++) h[tid + k * 128] = 0;
    __syncthreads();

    // ---- phase A: key + payload + block histogram ----
    const int i = myb * 128 + tid;
    const float gp0 = (pos[3*i+0] + 1.0f) * 63.5f;
    const float gp1 = (pos[3*i+1] + 1.0f) * 63.5f;
    const float gp2 = (pos[3*i+2] + 1.0f) * 63.5f;
    const int c0 = min(max((int)floorf(gp0), 0), GDIM-1);
    const int c1 = min(max((int)floorf(gp1), 0), GDIM-1);
    const int c2 = min(max((int)floorf(gp2), 0), GDIM-1);
    const int pc  = c0 | (c1 << 8) | (c2 << 16);
    const int key = ((c0 >> 2) << 4) | (c1 >> 3);
    atomicAdd(&h[key], 1);
    const float4 pA = make_float4(gp0, gp1, gp2, inten[i] * 0.01f);
    const float4 pE = make_float4(emo[4*i+0], emo[4*i+1], emo[4*i+2], emo[4*i+3]);
    __syncthreads();
#pragma unroll
    for (int k = 0; k < NKEY / 128; k++) {
        const int t = tid + k * 128;
        g_hist[myb * NKEY + t] = h[t];
    }
    __threadfence();

    // ---- barrier: all block histograms visible ----
    if (tid == 0) {
        atomicAdd(&g_bar1, 1);
        while (*(volatile int*)&g_bar1 < NBLK) { }
    }
    __syncthreads();
    __threadfence();

    // ---- phase B: per-key cross-block sums; thread t owns keys 4t..4t+3 ----
    int totk[4], bok[4];
#pragma unroll
    for (int k = 0; k < 4; k++) {
        const int kk = tid * 4 + k;
        int s = 0, mine = 0;
#pragma unroll
        for (int b = 0; b < NBLK; b++) {
            if (b == myb) mine = s;
            s += g_hist[b * NKEY + kk];
        }
        totk[k] = s; bok[k] = mine;
    }
    const int tsum = totk[0] + totk[1] + totk[2] + totk[3];
    int inc = tsum;
#pragma unroll
    for (int d = 1; d < 32; d <<= 1) {
        const int u = __shfl_up_sync(FULL, inc, d);
        if (lane >= d) inc += u;
    }
    if (lane == 31) wsum[w] = inc;
    __syncthreads();
    if (tid == 0) {
        int s = 0;
#pragma unroll
        for (int q = 0; q < 4; q++) { const int x = wsum[q]; wsum[q] = s; s += x; }
    }
    __syncthreads();
    int run = wsum[w] + inc - tsum;        // exclusive prefix for key 4*tid
#pragma unroll
    for (int k = 0; k < 4; k++) {
        const int kk = tid * 4 + k;
        bs2s[kk]  = run;
        boffm[kk] = bok[k];
        run += totk[k];
    }
    __syncthreads();
    if (myb == 0) {
#pragma unroll
        for (int k = 0; k < 4; k++) {
            const int kk = tid * 4 + k;
            g_bs2[kk] = bs2s[kk];
        }
        if (tid == 0) g_bs2[NKEY] = NPART;
    }

    // ---- phase C: stable in-block ranks + scatter ----
#pragma unroll
    for (int k = 0; k < 4 * NKEY / 128; k++) ((int*)wcnt)[tid + k * 128] = 0;
    __syncthreads();
    const unsigned m = __match_any_sync(FULL, key);
    const int r = __popc(m & ((1u << lane) - 1u));
    if (r == 0) wcnt[w][key] = __popc(m);
    __syncthreads();
#pragma unroll
    for (int k = 0; k < NKEY / 128; k++) {
        const int t = tid + k * 128;
        int s = 0;
#pragma unroll
        for (int wi = 0; wi < 4; wi++) { const int v = wcnt[wi][t]; wcnt[wi][t] = s; s += v; }
    }
    __syncthreads();

    const int p = bs2s[key] + boffm[key] + wcnt[w][key] + r;
    g_pcs[p]      = pc;
    g_ps[2*p + 0] = pA;
    g_ps[2*p + 1] = pE;

    // ---- self-reset barrier counters for next replay ----
    __syncthreads();
    if (tid == 0) {
        const int v = atomicAdd(&g_bar2, 1);
        if (v == NBLK - 1) { g_bar1 = 0; g_bar2 = 0; __threadfence(); }
    }
}

// ---------------------------------------------------------------------------
// ONE WARP PER BLOCK, one sample per warp. Each lane owns ONE of the 32
// needed cells (8 trilinear corners + 24 face neighbors).
// Chunk hit test is SIMD (vsub4/vcmpleu4); hit bodies are software-pipelined
// 1-deep so each hit's math hides the next hit's loads.
// ---------------------------------------------------------------------------
__global__ void __launch_bounds__(32)
main_kernel(const float* __restrict__ spos,
            const float* __restrict__ H0,
            const float* __restrict__ E0,
            float* __restrict__ out) {
    __shared__ float sv[5][64];
    const unsigned FULL = 0xffffffffu;
    const int lane = threadIdx.x;
    const int s    = blockIdx.x;

    const float px = spos[3*s+0];
    const float py = spos[3*s+1];
    const float pz = spos[3*s+2];
    // grid axis0 <- comp2, axis1 <- comp1, axis2 <- comp0 (reference transpose)
    const float t0 = fminf(fmaxf((pz + 1.0f) * 63.5f, 0.0f), 127.0f);
    const float t1 = fminf(fmaxf((py + 1.0f) * 63.5f, 0.0f), 127.0f);
    const float t2 = fminf(fmaxf((px + 1.0f) * 63.5f, 0.0f), 127.0f);
    const int i0 = (int)floorf(t0); const float f0 = t0 - (float)i0;
    const int i1 = (int)floorf(t1); const float f1 = t1 - (float)i1;
    const int i2 = (int)floorf(t2); const float f2 = t2 - (float)i2;

    // lane -> block coords (b0,b1,b2), covering the 32 needed cells
    int b0, b1, b2;
    if (lane < 8) {
        b0 = 1 + ((lane >> 2) & 1); b1 = 1 + ((lane >> 1) & 1); b2 = 1 + (lane & 1);
    } else {
        const int idx = lane - 8, axis = idx >> 3, rest = idx & 7;
        const int s3 = ((rest >> 2) & 1) * 3;
        const int u = 1 + ((rest >> 1) & 1), v = 1 + (rest & 1);
        b0 = (axis == 0) ? s3 : u;
        b1 = (axis == 1) ? s3 : ((axis == 0) ? u : v);
        b2 = (axis == 2) ? s3 : v;
    }
    const int gc0 = min(max(i0 - 1 + b0, 0), 127);
    const int gc1 = min(max(i1 - 1 + b1, 0), 127);
    const int gc2 = min(max(i2 - 1 + b2, 0), 127);
    const float gcf0 = (float)gc0, gcf1 = (float)gc1, gcf2 = (float)gc2;
    const unsigned gcpack = (unsigned)(gc0 | (gc1 << 8) | (gc2 << 16));

    // particle-window (covers all 32 cells)
    const int lo0 = min(max(i0 - 1, 0), 127) - 9, hi0 = min(max(i0 + 2, 0), 127) + 9;
    const int lo1 = min(max(i1 - 1, 0), 127) - 9, hi1 = min(max(i1 + 2, 0), 127) + 9;
    const int lo2 = min(max(i2 - 1, 0), 127) - 9, hi2 = min(max(i2 + 2, 0), 127) + 9;

    // SIMD window test constants: per-byte (c - lo) mod 256 <= sp.
    // Safe because spans <= 40 and lo - c <= 136 -> no mod-256 aliasing.
    const unsigned lopack = (unsigned)((lo0 & 255) | ((lo1 & 255) << 8) | ((lo2 & 255) << 16));
    const unsigned sppack = (unsigned)((hi0 - lo0) | ((hi1 - lo1) << 8) |
                                       ((hi2 - lo2) << 16)) | 0xFF000000u;

    const int r0  = max(lo0, 0) >> 2;
    const int r1  = min(hi0, 127) >> 2;
    const int slo = max(lo1, 0) >> 3;
    const int shi = min(hi1, 127) >> 3;
    const int nseg = r1 - r0;              // 0..6

    // ---- one MLP burst: all segment bounds + first-chunk cell words ----
    int jj0[SEGN], jj1[SEGN], pv[SEGN];
#pragma unroll
    for (int k = 0; k < SEGN; k++) {
        const bool val = (k <= nseg);
        const int rb = (r0 + k) << 4;
        jj0[k] = val ? __ldg(&g_bs2[rb + slo])     : 0;
        jj1[k] = val ? __ldg(&g_bs2[rb + shi + 1]) : 0;
    }
#pragma unroll
    for (int k = 0; k < SEGN; k++) {
        const bool val = (k <= nseg);
        pv[k] = __ldg(&g_pcs[(val ? (jj0[k] & ~31) : 0) + lane]);
    }

    // accumulators start from the base grid values (loads overlap the scan)
    const int flat = (gc0 * GDIM + gc1) * GDIM + gc2;
    float aH  = __ldg(&H0[flat]);
    float aE0 = __ldg(&E0[0*G3 + flat]);
    float aE1 = __ldg(&E0[1*G3 + flat]);
    float aE2 = __ldg(&E0[2*G3 + flat]);
    float aE3 = __ldg(&E0[3*G3 + flat]);

    // per-hit math (operands were loaded one pipeline stage earlier)
    auto process = [&](const float4& A, const float4& Em, int pcj) {
        const unsigned diff = __vabsdiffu4((unsigned)pcj, gcpack);
        const bool in = (__vcmpleu4(diff, 0x09090909u) == 0xFFFFFFFFu);
        const float d0 = gcf0 - A.x;
        const float d1 = gcf1 - A.y;
        const float d2 = gcf2 - A.z;
        const float ssum = fmaf(d0, d0, fmaf(d1, d1, d2 * d2));
        const float e = __expf(ssum * -0.048828125f);
        float wv = in ? A.w : 0.0f;
        wv *= e;
        aH  += wv;
        aE0 += wv * Em.x;  aE1 += wv * Em.y;
        aE2 += wv * Em.z;  aE3 += wv * Em.w;
    };

#pragma unroll
    for (int k = 0; k < SEGN; k++) {
        if (k > nseg) break;
        const int j0 = jj0[k], j1 = jj1[k];
        int base = j0 & ~31;
        int pcv  = pv[k];
        while (true) {
            const int  nbase = base + 32;
            const bool more  = nbase < j1;
            int npcv = 0;
            if (more) npcv = __ldg(&g_pcs[nbase + lane]);   // prefetch next chunk
            const int idx = base + lane;
            const bool hit = (__vcmpleu4(__vsub4((unsigned)pcv, lopack), sppack)
                              == 0xFFFFFFFFu) &
                             (idx >= j0) & (idx < j1);
            unsigned msk = __ballot_sync(FULL, hit);
            if (msk) {
                // 1-deep software pipeline over the hits of this chunk
                int j = __ffs(msk) - 1;
                msk &= msk - 1;
                float4 A   = __ldg(&g_ps[2*(base + j) + 0]);
                float4 Em  = __ldg(&g_ps[2*(base + j) + 1]);
                int    pcj = __shfl_sync(FULL, pcv, j);
                while (msk) {
                    const int jn = __ffs(msk) - 1;
                    msk &= msk - 1;
                    const float4 An  = __ldg(&g_ps[2*(base + jn) + 0]);
                    const float4 Emn = __ldg(&g_ps[2*(base + jn) + 1]);
                    const int    pcn = __shfl_sync(FULL, pcv, jn);
                    process(A, Em, pcj);
                    A = An; Em = Emn; pcj = pcn;
                }
                process(A, Em, pcj);
            }
            if (!more) break;
            base = nbase; pcv = npcv;
        }
    }

    // stash the 32 needed cells in shared
    const int ci = b0 * 16 + b1 * 4 + b2;
    sv[0][ci] = aH;
    sv[1][ci] = aE0;
    sv[2][ci] = aE1;
    sv[3][ci] = aE2;
    sv[4][ci] = aE3;
    __syncwarp();

    // diffusion step + ReLU + trilinear reduce (8 corner lanes)
#pragma unroll
    for (int ch = 0; ch < 5; ch++) {
        float part = 0.0f;
        if (lane < 8) {
            const int d0 = (lane >> 2) & 1, d1c = (lane >> 1) & 1, d2c = lane & 1;
            const int cc = (1 + d0) * 16 + (1 + d1c) * 4 + (1 + d2c);
            const float* v = sv[ch];
            const float c = v[cc];
            const float lap = v[cc-16] + v[cc+16] + v[cc-4] + v[cc+4]
                            + v[cc-1]  + v[cc+1]  - 6.0f * c;
            float val;
            if (ch == 0) val = c * (1.0f - 5e-5f) + 0.002f * lap;
            else         val = c * (1.0f - 5e-5f) + 5e-5f + 0.001f * lap;
            val = fmaxf(val, 0.0f);
            const float wq = (d0  ? f0 : 1.0f - f0)
                           * (d1c ? f1 : 1.0f - f1)
                           * (d2c ? f2 : 1.0f - f2);
            part = val * wq;
        }
        part += __shfl_down_sync(FULL, part, 4);
        part += __shfl_down_sync(FULL, part, 2);
        part += __shfl_down_sync(FULL, part, 1);
        if (lane == 0) out[s * 5 + ch] = part;
    }
}

extern "C" void kernel_launch(void* const* d_in, const int* in_sizes, int n_in,
                              void* d_out, int out_size) {
    const float* positions   = (const float*)d_in[0];  // (4096,3)
    const float* intensities = (const float*)d_in[1];  // (4096,)
    const float* emotions    = (const float*)d_in[2];  // (4096,4)
    const float* sample_pos  = (const float*)d_in[3];  // (8,1024,3)
    const float* H0          = (const float*)d_in[4];  // (128,128,128)
    const float* E0          = (const float*)d_in[5];  // (4,128,128,128)
    float* out = (float*)d_out;                        // (8,1024,5)

    fsort_kernel<<<NBLK, 128>>>(positions, intensities, emotions);
    main_kernel<<<8192, 32>>>(sample_pos, H0, E0, out);
    (void)in_sizes; (void)n_in; (void)out_size;
}

// round 13
// speedup vs baseline: 1.1227x; 1.0556x over previous
#include <cuda_runtime.h>
#include <math.h>

#define GDIM 128
#define G3 (GDIM*GDIM*GDIM)
#define NPART 4096
#define NKEY 512           // 32 c0-bins (width 4) x 16 c1-subbins (width 8)
#define NBLK2 8            // sort blocks (512 particles each)
#define SEGN 7             // max c0-bin segments per sample window

// Scratch (__device__ globals, no allocation)
__device__ float4 g_ps[NPART * 2];      // [2p]=(gp0,gp1,gp2,omega) [2p+1]=(em0..3)
__device__ int    g_pcs[NPART + 32];    // packed floor cell
__device__ int    g_bs2[NKEY + 1];      // key -> global start offset
__device__ int    g_hist[NBLK2 * NKEY]; // per-block key histograms
__device__ int    g_bar1;               // spin barrier (self-resetting)
__device__ int    g_bar2;

// lane -> packed cell byte: (b0<<4 | b1<<2 | b2) == ci = b0*16+b1*4+b2.
// Lanes 0-7: the 8 trilinear corners {1,2}^3; lanes 8-31: 24 face neighbors.
__constant__ unsigned char LTAB[32] = {
    0x15,0x16,0x19,0x1A,0x25,0x26,0x29,0x2A,      // corners
    0x05,0x06,0x09,0x0A,0x35,0x36,0x39,0x3A,      // axis0 faces
    0x11,0x12,0x21,0x22,0x1D,0x1E,0x2D,0x2E,      // axis1 faces
    0x14,0x18,0x24,0x28,0x17,0x1B,0x27,0x2B       // axis2 faces
};

// ---------------------------------------------------------------------------
// Fused sort: 8 blocks x 512 threads, 1 particle/thread.
// hist + cross-block offsets + stable scatter with a device spin barrier.
// ---------------------------------------------------------------------------
__global__ void __launch_bounds__(512)
fsort_kernel(const float* __restrict__ pos,
             const float* __restrict__ inten,
             const float* __restrict__ emo) {
    __shared__ int h[NKEY];
    __shared__ int bs2s[NKEY];
    __shared__ unsigned short boffm[NKEY];
    __shared__ unsigned short wcnt[16][NKEY];   // 16KB
    __shared__ int wsum[16];
    const int tid  = threadIdx.x;
    const int w    = tid >> 5;       // 0..15
    const int lane = tid & 31;
    const int myb  = blockIdx.x;
    const unsigned FULL = 0xffffffffu;

    h[tid] = 0;                      // NKEY == 512 == blockDim
    __syncthreads();

    // ---- phase A: key + payload + block histogram ----
    const int i = myb * 512 + tid;
    const float gp0 = (pos[3*i+0] + 1.0f) * 63.5f;
    const float gp1 = (pos[3*i+1] + 1.0f) * 63.5f;
    const float gp2 = (pos[3*i+2] + 1.0f) * 63.5f;
    const int c0 = min(max((int)floorf(gp0), 0), GDIM-1);
    const int c1 = min(max((int)floorf(gp1), 0), GDIM-1);
    const int c2 = min(max((int)floorf(gp2), 0), GDIM-1);
    const int pc  = c0 | (c1 << 8) | (c2 << 16);
    const int key = ((c0 >> 2) << 4) | (c1 >> 3);
    atomicAdd(&h[key], 1);
    const float4 pA = make_float4(gp0, gp1, gp2, inten[i] * 0.01f);
    const float4 pE = make_float4(emo[4*i+0], emo[4*i+1], emo[4*i+2], emo[4*i+3]);
    __syncthreads();
    g_hist[myb * NKEY + tid] = h[tid];
    __threadfence();

    // ---- barrier: all block histograms visible ----
    if (tid == 0) {
        atomicAdd(&g_bar1, 1);
        while (*(volatile int*)&g_bar1 < NBLK2) { }
    }
    __syncthreads();
    __threadfence();

    // ---- phase B: thread t owns key t ----
    int tot = 0, mine = 0;
#pragma unroll
    for (int b = 0; b < NBLK2; b++) {
        const int v = g_hist[b * NKEY + tid];
        if (b == myb) mine = tot;
        tot += v;
    }
    int inc = tot;
#pragma unroll
    for (int d = 1; d < 32; d <<= 1) {
        const int u = __shfl_up_sync(FULL, inc, d);
        if (lane >= d) inc += u;
    }
    if (lane == 31) wsum[w] = inc;
    __syncthreads();
    if (tid == 0) {
        int s = 0;
#pragma unroll
        for (int q = 0; q < 16; q++) { const int x = wsum[q]; wsum[q] = s; s += x; }
    }
    __syncthreads();
    bs2s[tid]  = wsum[w] + inc - tot;      // global exclusive prefix for key tid
    boffm[tid] = (unsigned short)mine;
    if (myb == 0) {
        g_bs2[tid] = wsum[w] + inc - tot;
        if (tid == 0) g_bs2[NKEY] = NPART;
    }

    // ---- phase C: stable in-block ranks + scatter ----
    __syncthreads();
#pragma unroll
    for (int k = 0; k < 16 * NKEY / 512 / 2; k++)   // 16KB as ints
        ((int*)wcnt)[tid + k * 512] = 0;
    __syncthreads();
    const unsigned m = __match_any_sync(FULL, key);
    const int r = __popc(m & ((1u << lane) - 1u));
    if (r == 0) wcnt[w][key] = (unsigned short)__popc(m);
    __syncthreads();
    {
        int s = 0;
#pragma unroll
        for (int wi = 0; wi < 16; wi++) {
            const int v = wcnt[wi][tid];
            wcnt[wi][tid] = (unsigned short)s;
            s += v;
        }
    }
    __syncthreads();

    const int p = bs2s[key] + (int)boffm[key] + (int)wcnt[w][key] + r;
    g_pcs[p]      = pc;
    g_ps[2*p + 0] = pA;
    g_ps[2*p + 1] = pE;

    // ---- self-reset barrier counters for next replay ----
    __syncthreads();
    if (tid == 0) {
        const int v = atomicAdd(&g_bar2, 1);
        if (v == NBLK2 - 1) { g_bar1 = 0; g_bar2 = 0; __threadfence(); }
    }
}

// ---------------------------------------------------------------------------
// ONE WARP PER BLOCK, one sample per warp. Lane -> cell via LTAB.
// SIMD chunk test + 1-deep software-pipelined hit bodies.
// Epilogue: 2-pass (4ch x 8corners across 32 lanes, then ch4 on 8 lanes).
// ---------------------------------------------------------------------------
__global__ void __launch_bounds__(32)
main_kernel(const float* __restrict__ spos,
            const float* __restrict__ H0,
            const float* __restrict__ E0,
            float* __restrict__ out) {
    __shared__ float sv[5][64];
    const unsigned FULL = 0xffffffffu;
    const int lane = threadIdx.x;
    const int s    = blockIdx.x;

    const float px = spos[3*s+0];
    const float py = spos[3*s+1];
    const float pz = spos[3*s+2];
    // grid axis0 <- comp2, axis1 <- comp1, axis2 <- comp0 (reference transpose)
    const float t0 = fminf(fmaxf((pz + 1.0f) * 63.5f, 0.0f), 127.0f);
    const float t1 = fminf(fmaxf((py + 1.0f) * 63.5f, 0.0f), 127.0f);
    const float t2 = fminf(fmaxf((px + 1.0f) * 63.5f, 0.0f), 127.0f);
    const int i0 = (int)floorf(t0); const float f0 = t0 - (float)i0;
    const int i1 = (int)floorf(t1); const float f1 = t1 - (float)i1;
    const int i2 = (int)floorf(t2); const float f2 = t2 - (float)i2;

    // lane -> block coords via packed constant (byte == ci)
    const int tb = (int)LTAB[lane];
    const int b0 = tb >> 4, b1 = (tb >> 2) & 3, b2 = tb & 3;

    const int gc0 = min(max(i0 - 1 + b0, 0), 127);
    const int gc1 = min(max(i1 - 1 + b1, 0), 127);
    const int gc2 = min(max(i2 - 1 + b2, 0), 127);
    const float gcf0 = (float)gc0, gcf1 = (float)gc1, gcf2 = (float)gc2;
    const unsigned gcpack = (unsigned)(gc0 | (gc1 << 8) | (gc2 << 16));

    // particle-window (covers all 32 cells)
    const int lo0 = min(max(i0 - 1, 0), 127) - 9, hi0 = min(max(i0 + 2, 0), 127) + 9;
    const int lo1 = min(max(i1 - 1, 0), 127) - 9, hi1 = min(max(i1 + 2, 0), 127) + 9;
    const int lo2 = min(max(i2 - 1, 0), 127) - 9, hi2 = min(max(i2 + 2, 0), 127) + 9;

    // SIMD window test constants: per-byte (c - lo) mod 256 <= sp.
    const unsigned lopack = (unsigned)((lo0 & 255) | ((lo1 & 255) << 8) | ((lo2 & 255) << 16));
    const unsigned sppack = (unsigned)((hi0 - lo0) | ((hi1 - lo1) << 8) |
                                       ((hi2 - lo2) << 16)) | 0xFF000000u;

    const int r0  = max(lo0, 0) >> 2;
    const int r1  = min(hi0, 127) >> 2;
    const int slo = max(lo1, 0) >> 3;
    const int shi = min(hi1, 127) >> 3;
    const int nseg = r1 - r0;              // 0..6

    // ---- one MLP burst: all segment bounds + first-chunk cell words ----
    int jj0[SEGN], jj1[SEGN], pv[SEGN];
#pragma unroll
    for (int k = 0; k < SEGN; k++) {
        const bool val = (k <= nseg);
        const int rb = (r0 + k) << 4;
        jj0[k] = val ? __ldg(&g_bs2[rb + slo])     : 0;
        jj1[k] = val ? __ldg(&g_bs2[rb + shi + 1]) : 0;
    }
#pragma unroll
    for (int k = 0; k < SEGN; k++) {
        const bool val = (k <= nseg);
        pv[k] = __ldg(&g_pcs[(val ? (jj0[k] & ~31) : 0) + lane]);
    }

    // accumulators start from the base grid values (loads overlap the scan)
    const int flat = (gc0 * GDIM + gc1) * GDIM + gc2;
    float aH  = __ldg(&H0[flat]);
    float aE0 = __ldg(&E0[0*G3 + flat]);
    float aE1 = __ldg(&E0[1*G3 + flat]);
    float aE2 = __ldg(&E0[2*G3 + flat]);
    float aE3 = __ldg(&E0[3*G3 + flat]);

    // per-hit math (operands loaded one pipeline stage earlier)
    auto process = [&](const float4& A, const float4& Em, int pcj) {
        const unsigned diff = __vabsdiffu4((unsigned)pcj, gcpack);
        const bool in = (__vcmpleu4(diff, 0x09090909u) == 0xFFFFFFFFu);
        const float d0 = gcf0 - A.x;
        const float d1 = gcf1 - A.y;
        const float d2 = gcf2 - A.z;
        const float ssum = fmaf(d0, d0, fmaf(d1, d1, d2 * d2));
        const float e = __expf(ssum * -0.048828125f);
        float wv = in ? A.w : 0.0f;
        wv *= e;
        aH  += wv;
        aE0 += wv * Em.x;  aE1 += wv * Em.y;
        aE2 += wv * Em.z;  aE3 += wv * Em.w;
    };

#pragma unroll
    for (int k = 0; k < SEGN; k++) {
        if (k > nseg) break;
        const int j0 = jj0[k], j1 = jj1[k];
        int base = j0 & ~31;
        int pcv  = pv[k];
        while (true) {
            const int  nbase = base + 32;
            const bool more  = nbase < j1;
            int npcv = 0;
            if (more) npcv = __ldg(&g_pcs[nbase + lane]);   // prefetch next chunk
            const int idx = base + lane;
            const bool hit = (__vcmpleu4(__vsub4((unsigned)pcv, lopack), sppack)
                              == 0xFFFFFFFFu) &
                             (idx >= j0) & (idx < j1);
            unsigned msk = __ballot_sync(FULL, hit);
            if (msk) {
                int j = __ffs(msk) - 1;
                msk &= msk - 1;
                float4 A   = __ldg(&g_ps[2*(base + j) + 0]);
                float4 Em  = __ldg(&g_ps[2*(base + j) + 1]);
                int    pcj = __shfl_sync(FULL, pcv, j);
                while (msk) {
                    const int jn = __ffs(msk) - 1;
                    msk &= msk - 1;
                    const float4 An  = __ldg(&g_ps[2*(base + jn) + 0]);
                    const float4 Emn = __ldg(&g_ps[2*(base + jn) + 1]);
                    const int    pcn = __shfl_sync(FULL, pcv, jn);
                    process(A, Em, pcj);
                    A = An; Em = Emn; pcj = pcn;
                }
                process(A, Em, pcj);
            }
            if (!more) break;
            base = nbase; pcv = npcv;
        }
    }

    // stash the 32 needed cells in shared (ci == tb)
    sv[0][tb] = aH;
    sv[1][tb] = aE0;
    sv[2][tb] = aE1;
    sv[3][tb] = aE2;
    sv[4][tb] = aE3;
    __syncwarp();

    // ---- epilogue pass 1: channels 0..3 across all 32 lanes ----
    {
        const int ch  = lane >> 3;          // 0..3
        const int cor = lane & 7;
        const int d0 = (cor >> 2) & 1, d1c = (cor >> 1) & 1, d2c = cor & 1;
        const int cc = (1 + d0) * 16 + (1 + d1c) * 4 + (1 + d2c);
        const float* v = sv[ch];
        const float c = v[cc];
        const float lap = v[cc-16] + v[cc+16] + v[cc-4] + v[cc+4]
                        + v[cc-1]  + v[cc+1]  - 6.0f * c;
        const float alpha = (ch == 0) ? 0.002f : 0.001f;
        const float add   = (ch == 0) ? 0.0f   : 5e-5f;
        float val = fmaxf(fmaf(c, 1.0f - 5e-5f, fmaf(alpha, lap, add)), 0.0f);
        const float wq = (d0  ? f0 : 1.0f - f0)
                       * (d1c ? f1 : 1.0f - f1)
                       * (d2c ? f2 : 1.0f - f2);
        float part = val * wq;
        part += __shfl_down_sync(FULL, part, 4, 8);
        part += __shfl_down_sync(FULL, part, 2, 8);
        part += __shfl_down_sync(FULL, part, 1, 8);
        if (cor == 0) out[s * 5 + ch] = part;
    }
    // ---- epilogue pass 2: channel 4 on lanes 0..7 ----
    {
        float part = 0.0f;
        if (lane < 8) {
            const int d0 = (lane >> 2) & 1, d1c = (lane >> 1) & 1, d2c = lane & 1;
            const int cc = (1 + d0) * 16 + (1 + d1c) * 4 + (1 + d2c);
            const float* v = sv[4];
            const float c = v[cc];
            const float lap = v[cc-16] + v[cc+16] + v[cc-4] + v[cc+4]
                            + v[cc-1]  + v[cc+1]  - 6.0f * c;
            float val = fmaxf(fmaf(c, 1.0f - 5e-5f, fmaf(0.001f, lap, 5e-5f)), 0.0f);
            const float wq = (d0  ? f0 : 1.0f - f0)
                           * (d1c ? f1 : 1.0f - f1)
                           * (d2c ? f2 : 1.0f - f2);
            part = val * wq;
        }
        part += __shfl_down_sync(FULL, part, 4, 8);
        part += __shfl_down_sync(FULL, part, 2, 8);
        part += __shfl_down_sync(FULL, part, 1, 8);
        if (lane == 0) out[s * 5 + 4] = part;
    }
}

extern "C" void kernel_launch(void* const* d_in, const int* in_sizes, int n_in,
                              void* d_out, int out_size) {
    const float* positions   = (const float*)d_in[0];  // (4096,3)
    const float* intensities = (const float*)d_in[1];  // (4096,)
    const float* emotions    = (const float*)d_in[2];  // (4096,4)
    const float* sample_pos  = (const float*)d_in[3];  // (8,1024,3)
    const float* H0          = (const float*)d_in[4];  // (128,128,128)
    const float* E0          = (const float*)d_in[5];  // (4,128,128,128)
    float* out = (float*)d_out;                        // (8,1024,5)

    fsort_kernel<<<NBLK2, 512>>>(positions, intensities, emotions);
    main_kernel<<<8192, 32>>>(sample_pos, H0, E0, out);
    (void)in_sizes; (void)n_in; (void)out_size;
}

// round 14
// speedup vs baseline: 1.2010x; 1.0697x over previous
#include <cuda_runtime.h>
#include <math.h>

#define GDIM 128
#define G3 (GDIM*GDIM*GDIM)
#define NPART 4096
#define NKEY 512           // 32 c0-bins (width 4) x 16 c1-subbins (width 8)
#define NBLK2 8            // sort blocks (512 particles each)
#define SEGN 7             // max c0-bin segments per sample window

// Scratch (__device__ globals, no allocation)
__device__ float4 g_ps[NPART * 2];      // [2p]=(gp0,gp1,gp2,omega) [2p+1]=(em0..3)
__device__ int    g_pcs[NPART + 32];    // packed floor cell (+pad)
__device__ int    g_bs2[NKEY + 1];      // key -> global start offset
__device__ int    g_hist[NBLK2 * NKEY]; // per-block key histograms
__device__ int    g_bar1;               // spin barrier (self-resetting)
__device__ int    g_bar2;

// lane -> packed cell byte: (b0<<4 | b1<<2 | b2) == ci = b0*16+b1*4+b2.
// Lanes 0-7: the 8 trilinear corners {1,2}^3; lanes 8-31: 24 face neighbors.
__constant__ unsigned char LTAB[32] = {
    0x15,0x16,0x19,0x1A,0x25,0x26,0x29,0x2A,      // corners
    0x05,0x06,0x09,0x0A,0x35,0x36,0x39,0x3A,      // axis0 faces
    0x11,0x12,0x21,0x22,0x1D,0x1E,0x2D,0x2E,      // axis1 faces
    0x14,0x18,0x24,0x28,0x17,0x1B,0x27,0x2B       // axis2 faces
};

// ---------------------------------------------------------------------------
// Fused sort: 8 blocks x 512 threads, 1 particle/thread.
// hist + cross-block offsets + stable scatter with a device spin barrier.
// ---------------------------------------------------------------------------
__global__ void __launch_bounds__(512)
fsort_kernel(const float* __restrict__ pos,
             const float* __restrict__ inten,
             const float* __restrict__ emo) {
    __shared__ int h[NKEY];
    __shared__ int bs2s[NKEY];
    __shared__ unsigned short boffm[NKEY];
    __shared__ unsigned short wcnt[16][NKEY];   // 16KB
    __shared__ int wsum[16];
    const int tid  = threadIdx.x;
    const int w    = tid >> 5;       // 0..15
    const int lane = tid & 31;
    const int myb  = blockIdx.x;
    const unsigned FULL = 0xffffffffu;

    h[tid] = 0;                      // NKEY == 512 == blockDim
    __syncthreads();

    // ---- phase A: key + payload + block histogram ----
    const int i = myb * 512 + tid;
    const float gp0 = (pos[3*i+0] + 1.0f) * 63.5f;
    const float gp1 = (pos[3*i+1] + 1.0f) * 63.5f;
    const float gp2 = (pos[3*i+2] + 1.0f) * 63.5f;
    const int c0 = min(max((int)floorf(gp0), 0), GDIM-1);
    const int c1 = min(max((int)floorf(gp1), 0), GDIM-1);
    const int c2 = min(max((int)floorf(gp2), 0), GDIM-1);
    const int pc  = c0 | (c1 << 8) | (c2 << 16);
    const int key = ((c0 >> 2) << 4) | (c1 >> 3);
    atomicAdd(&h[key], 1);
    const float4 pA = make_float4(gp0, gp1, gp2, inten[i] * 0.01f);
    const float4 pE = make_float4(emo[4*i+0], emo[4*i+1], emo[4*i+2], emo[4*i+3]);
    __syncthreads();
    g_hist[myb * NKEY + tid] = h[tid];
    __threadfence();

    // ---- barrier: all block histograms visible ----
    if (tid == 0) {
        atomicAdd(&g_bar1, 1);
        while (*(volatile int*)&g_bar1 < NBLK2) { }
    }
    __syncthreads();
    __threadfence();

    // ---- phase B: thread t owns key t ----
    int tot = 0, mine = 0;
#pragma unroll
    for (int b = 0; b < NBLK2; b++) {
        const int v = g_hist[b * NKEY + tid];
        if (b == myb) mine = tot;
        tot += v;
    }
    int inc = tot;
#pragma unroll
    for (int d = 1; d < 32; d <<= 1) {
        const int u = __shfl_up_sync(FULL, inc, d);
        if (lane >= d) inc += u;
    }
    if (lane == 31) wsum[w] = inc;
    __syncthreads();
    if (tid == 0) {
        int s = 0;
#pragma unroll
        for (int q = 0; q < 16; q++) { const int x = wsum[q]; wsum[q] = s; s += x; }
    }
    __syncthreads();
    bs2s[tid]  = wsum[w] + inc - tot;      // global exclusive prefix for key tid
    boffm[tid] = (unsigned short)mine;
    if (myb == 0) {
        g_bs2[tid] = wsum[w] + inc - tot;
        if (tid == 0) g_bs2[NKEY] = NPART;
    }

    // ---- phase C: stable in-block ranks + scatter ----
    __syncthreads();
#pragma unroll
    for (int k = 0; k < 16 * NKEY / 512 / 2; k++)   // 16KB as ints
        ((int*)wcnt)[tid + k * 512] = 0;
    __syncthreads();
    const unsigned m = __match_any_sync(FULL, key);
    const int r = __popc(m & ((1u << lane) - 1u));
    if (r == 0) wcnt[w][key] = (unsigned short)__popc(m);
    __syncthreads();
    {
        int s = 0;
#pragma unroll
        for (int wi = 0; wi < 16; wi++) {
            const int v = wcnt[wi][tid];
            wcnt[wi][tid] = (unsigned short)s;
            s += v;
        }
    }
    __syncthreads();

    const int p = bs2s[key] + (int)boffm[key] + (int)wcnt[w][key] + r;
    g_pcs[p]      = pc;
    g_ps[2*p + 0] = pA;
    g_ps[2*p + 1] = pE;

    // ---- self-reset barrier counters for next replay ----
    __syncthreads();
    if (tid == 0) {
        const int v = atomicAdd(&g_bar2, 1);
        if (v == NBLK2 - 1) { g_bar1 = 0; g_bar2 = 0; __threadfence(); }
    }
}

// ---------------------------------------------------------------------------
// ONE WARP PER BLOCK, one sample per warp. Lane -> cell via LTAB.
// EXACT unaligned segment scan [j0, j1) at lane granularity (no chunk
// alignment waste), SIMD chunk test, 1-deep software-pipelined hit bodies.
// ---------------------------------------------------------------------------
__global__ void __launch_bounds__(32)
main_kernel(const float* __restrict__ spos,
            const float* __restrict__ H0,
            const float* __restrict__ E0,
            float* __restrict__ out) {
    __shared__ float sv[5][64];
    const unsigned FULL = 0xffffffffu;
    const int lane = threadIdx.x;
    const int s    = blockIdx.x;

    const float px = spos[3*s+0];
    const float py = spos[3*s+1];
    const float pz = spos[3*s+2];
    // grid axis0 <- comp2, axis1 <- comp1, axis2 <- comp0 (reference transpose)
    const float t0 = fminf(fmaxf((pz + 1.0f) * 63.5f, 0.0f), 127.0f);
    const float t1 = fminf(fmaxf((py + 1.0f) * 63.5f, 0.0f), 127.0f);
    const float t2 = fminf(fmaxf((px + 1.0f) * 63.5f, 0.0f), 127.0f);
    const int i0 = (int)floorf(t0); const float f0 = t0 - (float)i0;
    const int i1 = (int)floorf(t1); const float f1 = t1 - (float)i1;
    const int i2 = (int)floorf(t2); const float f2 = t2 - (float)i2;

    // lane -> block coords via packed constant (byte == ci)
    const int tb = (int)LTAB[lane];
    const int b0 = tb >> 4, b1 = (tb >> 2) & 3, b2 = tb & 3;

    const int gc0 = min(max(i0 - 1 + b0, 0), 127);
    const int gc1 = min(max(i1 - 1 + b1, 0), 127);
    const int gc2 = min(max(i2 - 1 + b2, 0), 127);
    const float gcf0 = (float)gc0, gcf1 = (float)gc1, gcf2 = (float)gc2;
    const unsigned gcpack = (unsigned)(gc0 | (gc1 << 8) | (gc2 << 16));

    // particle-window (covers all 32 cells)
    const int lo0 = min(max(i0 - 1, 0), 127) - 9, hi0 = min(max(i0 + 2, 0), 127) + 9;
    const int lo1 = min(max(i1 - 1, 0), 127) - 9, hi1 = min(max(i1 + 2, 0), 127) + 9;
    const int lo2 = min(max(i2 - 1, 0), 127) - 9, hi2 = min(max(i2 + 2, 0), 127) + 9;

    // SIMD window test constants: per-byte (c - lo) mod 256 <= sp.
    const unsigned lopack = (unsigned)((lo0 & 255) | ((lo1 & 255) << 8) | ((lo2 & 255) << 16));
    const unsigned sppack = (unsigned)((hi0 - lo0) | ((hi1 - lo1) << 8) |
                                       ((hi2 - lo2) << 16)) | 0xFF000000u;

    const int r0  = max(lo0, 0) >> 2;
    const int r1  = min(hi0, 127) >> 2;
    const int slo = max(lo1, 0) >> 3;
    const int shi = min(hi1, 127) >> 3;
    const int nseg = r1 - r0;              // 0..6

    // ---- one MLP burst: all segment bounds + first-chunk cell words ----
    int jj0[SEGN], jj1[SEGN], pv[SEGN];
#pragma unroll
    for (int k = 0; k < SEGN; k++) {
        const bool val = (k <= nseg);
        const int rb = (r0 + k) << 4;
        jj0[k] = val ? __ldg(&g_bs2[rb + slo])     : 0;
        jj1[k] = val ? __ldg(&g_bs2[rb + shi + 1]) : 0;
    }
#pragma unroll
    for (int k = 0; k < SEGN; k++) {
        const bool val = (k <= nseg);
        pv[k] = __ldg(&g_pcs[(val ? jj0[k] : 0) + lane]);
    }

    // accumulators start from the base grid values (loads overlap the scan)
    const int flat = (gc0 * GDIM + gc1) * GDIM + gc2;
    float aH  = __ldg(&H0[flat]);
    float aE0 = __ldg(&E0[0*G3 + flat]);
    float aE1 = __ldg(&E0[1*G3 + flat]);
    float aE2 = __ldg(&E0[2*G3 + flat]);
    float aE3 = __ldg(&E0[3*G3 + flat]);

    // per-hit math (operands loaded one pipeline stage earlier)
    auto process = [&](const float4& A, const float4& Em, int pcj) {
        const unsigned diff = __vabsdiffu4((unsigned)pcj, gcpack);
        const bool in = (__vcmpleu4(diff, 0x09090909u) == 0xFFFFFFFFu);
        const float d0 = gcf0 - A.x;
        const float d1 = gcf1 - A.y;
        const float d2 = gcf2 - A.z;
        const float ssum = fmaf(d0, d0, fmaf(d1, d1, d2 * d2));
        const float e = __expf(ssum * -0.048828125f);
        float wv = in ? A.w : 0.0f;
        wv *= e;
        aH  += wv;
        aE0 += wv * Em.x;  aE1 += wv * Em.y;
        aE2 += wv * Em.z;  aE3 += wv * Em.w;
    };

#pragma unroll
    for (int k = 0; k < SEGN; k++) {
        if (k > nseg) break;
        const int j0 = jj0[k], j1 = jj1[k];
        const int j1lane = j1 - lane;      // bound in lane-local form
        int ibase = j0;
        int pcv   = pv[k];
        while (ibase < j1) {
            const int  nib  = ibase + 32;
            const bool more = nib < j1;
            int npcv = 0;
            if (more) npcv = __ldg(&g_pcs[nib + lane]);   // prefetch next chunk
            const bool hit = (__vcmpleu4(__vsub4((unsigned)pcv, lopack), sppack)
                              == 0xFFFFFFFFu) &
                             (ibase < j1lane);
            unsigned msk = __ballot_sync(FULL, hit);
            if (msk) {
                // 1-deep software pipeline over the hits of this chunk
                int j = __ffs(msk) - 1;
                msk &= msk - 1;
                float4 A   = __ldg(&g_ps[2*(ibase + j) + 0]);
                float4 Em  = __ldg(&g_ps[2*(ibase + j) + 1]);
                int    pcj = __shfl_sync(FULL, pcv, j);
                while (msk) {
                    const int jn = __ffs(msk) - 1;
                    msk &= msk - 1;
                    const float4 An  = __ldg(&g_ps[2*(ibase + jn) + 0]);
                    const float4 Emn = __ldg(&g_ps[2*(ibase + jn) + 1]);
                    const int    pcn = __shfl_sync(FULL, pcv, jn);
                    process(A, Em, pcj);
                    A = An; Em = Emn; pcj = pcn;
                }
                process(A, Em, pcj);
            }
            ibase = nib; pcv = npcv;
        }
    }

    // stash the 32 needed cells in shared (ci == tb)
    sv[0][tb] = aH;
    sv[1][tb] = aE0;
    sv[2][tb] = aE1;
    sv[3][tb] = aE2;
    sv[4][tb] = aE3;
    __syncwarp();

    // ---- epilogue pass 1: channels 0..3 across all 32 lanes ----
    {
        const int ch  = lane >> 3;          // 0..3
        const int cor = lane & 7;
        const int d0 = (cor >> 2) & 1, d1c = (cor >> 1) & 1, d2c = cor & 1;
        const int cc = (1 + d0) * 16 + (1 + d1c) * 4 + (1 + d2c);
        const float* v = sv[ch];
        const float c = v[cc];
        const float lap = v[cc-16] + v[cc+16] + v[cc-4] + v[cc+4]
                        + v[cc-1]  + v[cc+1]  - 6.0f * c;
        const float alpha = (ch == 0) ? 0.002f : 0.001f;
        const float add   = (ch == 0) ? 0.0f   : 5e-5f;
        float val = fmaxf(fmaf(c, 1.0f - 5e-5f, fmaf(alpha, lap, add)), 0.0f);
        const float wq = (d0  ? f0 : 1.0f - f0)
                       * (d1c ? f1 : 1.0f - f1)
                       * (d2c ? f2 : 1.0f - f2);
        float part = val * wq;
        part += __shfl_down_sync(FULL, part, 4, 8);
        part += __shfl_down_sync(FULL, part, 2, 8);
        part += __shfl_down_sync(FULL, part, 1, 8);
        if (cor == 0) out[s * 5 + ch] = part;
    }
    // ---- epilogue pass 2: channel 4 on lanes 0..7 ----
    {
        float part = 0.0f;
        if (lane < 8) {
            const int d0 = (lane >> 2) & 1, d1c = (lane >> 1) & 1, d2c = lane & 1;
            const int cc = (1 + d0) * 16 + (1 + d1c) * 4 + (1 + d2c);
            const float* v = sv[4];
            const float c = v[cc];
            const float lap = v[cc-16] + v[cc+16] + v[cc-4] + v[cc+4]
                            + v[cc-1]  + v[cc+1]  - 6.0f * c;
            float val = fmaxf(fmaf(c, 1.0f - 5e-5f, fmaf(0.001f, lap, 5e-5f)), 0.0f);
            const float wq = (d0  ? f0 : 1.0f - f0)
                           * (d1c ? f1 : 1.0f - f1)
                           * (d2c ? f2 : 1.0f - f2);
            part = val * wq;
        }
        part += __shfl_down_sync(FULL, part, 4, 8);
        part += __shfl_down_sync(FULL, part, 2, 8);
        part += __shfl_down_sync(FULL, part, 1, 8);
        if (lane == 0) out[s * 5 + 4] = part;
    }
}

extern "C" void kernel_launch(void* const* d_in, const int* in_sizes, int n_in,
                              void* d_out, int out_size) {
    const float* positions   = (const float*)d_in[0];  // (4096,3)
    const float* intensities = (const float*)d_in[1];  // (4096,)
    const float* emotions    = (const float*)d_in[2];  // (4096,4)
    const float* sample_pos  = (const float*)d_in[3];  // (8,1024,3)
    const float* H0          = (const float*)d_in[4];  // (128,128,128)
    const float* E0          = (const float*)d_in[5];  // (4,128,128,128)
    float* out = (float*)d_out;                        // (8,1024,5)

    fsort_kernel<<<NBLK2, 512>>>(positions, intensities, emotions);
    main_kernel<<<8192, 32>>>(sample_pos, H0, E0, out);
    (void)in_sizes; (void)n_in; (void)out_size;
}